// round 1
// baseline (speedup 1.0000x reference)
#include <cuda_runtime.h>

#define HD   64
#define VOC  64
#define SEQ  48
#define MSL  4
#define PADS 68   // padded row stride for token-indexed tables (68 % 32 == 4 -> spreads banks)

typedef unsigned long long u64;

// Precomputed layer-1 tables (scratch via __device__ globals; no allocation).
__device__ float gTA[VOC * HD];   // embed[v] @ W1[:, :64]^T + b1
__device__ float gTB[VOC * HD];   // 0.25 * embed[v] @ W1[:, 64:]^T

__device__ __forceinline__ u64 fma2(u64 a, u64 b, u64 c) {
    u64 d;
    asm("fma.rn.f32x2 %0, %1, %2, %3;" : "=l"(d) : "l"(a), "l"(b), "l"(c));
    return d;
}
__device__ __forceinline__ u64 add2(u64 a, u64 b) {
    u64 d;
    asm("add.rn.f32x2 %0, %1, %2;" : "=l"(d) : "l"(a), "l"(b));
    return d;
}
__device__ __forceinline__ void unpack2(u64 v, float& x, float& y) {
    asm("mov.b64 {%0, %1}, %2;" : "=f"(x), "=f"(y) : "l"(v));
}
__device__ __forceinline__ u64 pack2(float x, float y) {
    u64 v;
    asm("mov.b64 %0, {%1, %2};" : "=l"(v) : "f"(x), "f"(y));
    return v;
}

// ---------------------------------------------------------------------------
// Kernel 1: build the 64x64 layer-1 tables. grid = VOC blocks, 64 threads.
// Cost is ~1M FMA total -> negligible.
// ---------------------------------------------------------------------------
__global__ void precompute_tables(const float* __restrict__ embed,
                                  const float* __restrict__ W1,
                                  const float* __restrict__ b1) {
    int v = blockIdx.x;     // token value 0..63
    int j = threadIdx.x;    // output unit 0..63
    __shared__ float e[HD];
    if (j < HD) e[j] = embed[v * HD + j];
    __syncthreads();

    float sa = b1[j];
    float sb = 0.0f;
    const float* w = W1 + j * (2 * HD);   // W1 row j: [d<64 | d>=64]
#pragma unroll
    for (int d = 0; d < HD; d++) {
        sa = fmaf(e[d], w[d], sa);
        sb = fmaf(e[d], w[HD + d], sb);
    }
    gTA[v * HD + j] = sa;
    gTB[v * HD + j] = 0.25f * sb;   // fold the mean's 1/4
}

// ---------------------------------------------------------------------------
// Kernel 2: main. One thread per batch row.
//   s   = TA[q] + TB[t0] + TB[t1] + TB[t2] + TB[t3]     (packed f32x2 adds)
//   h   = relu(s)
//   out = h @ W2^T + b2                                  (packed fma.rn.f32x2)
// ---------------------------------------------------------------------------
__global__ void __launch_bounds__(256)
lru_main(const int* __restrict__ seqs,
         const int* __restrict__ query_tok,
         const float* __restrict__ W2,
         const float* __restrict__ b2,
         float* __restrict__ out,
         int Bn) {
    extern __shared__ float smem[];
    float* sTA = smem;                        // VOC * PADS
    float* sTB = sTA + VOC * PADS;            // VOC * PADS
    float* sW2 = sTB + VOC * PADS;            // 64 * 64 (unpadded: broadcast reads)
    float* sb2 = sW2 + HD * HD;               // 64

    // Cooperative fill of shared tables.
    for (int idx = threadIdx.x; idx < VOC * HD; idx += blockDim.x) {
        int r = idx >> 6, c = idx & 63;
        sTA[r * PADS + c] = gTA[idx];
        sTB[r * PADS + c] = gTB[idx];
        sW2[idx] = W2[idx];
    }
    if (threadIdx.x < HD) sb2[threadIdx.x] = b2[threadIdx.x];
    __syncthreads();

    int i = blockIdx.x * blockDim.x + threadIdx.x;
    if (i >= Bn) return;

    int q = query_tok[i];
    const int* sr = seqs + (long long)i * SEQ + (SEQ - 1 - MSL);
    int t0 = sr[0], t1 = sr[1], t2 = sr[2], t3 = sr[3];

    const ulonglong2* A  = (const ulonglong2*)(sTA + q  * PADS);
    const ulonglong2* B0 = (const ulonglong2*)(sTB + t0 * PADS);
    const ulonglong2* B1 = (const ulonglong2*)(sTB + t1 * PADS);
    const ulonglong2* B2 = (const ulonglong2*)(sTB + t2 * PADS);
    const ulonglong2* B3 = (const ulonglong2*)(sTB + t3 * PADS);

    // h as 32 packed f32x2 values (64 regs).
    u64 h2[32];
#pragma unroll
    for (int j = 0; j < 16; j++) {
        ulonglong2 a  = A[j];
        ulonglong2 p0 = B0[j], p1 = B1[j], p2 = B2[j], p3 = B3[j];
        u64 sx = add2(add2(a.x, p0.x), add2(add2(p1.x, p2.x), p3.x));
        u64 sy = add2(add2(a.y, p0.y), add2(add2(p1.y, p2.y), p3.y));
        float fx0, fx1, fy0, fy1;
        unpack2(sx, fx0, fx1);
        unpack2(sy, fy0, fy1);
        h2[2 * j + 0] = pack2(fmaxf(fx0, 0.0f), fmaxf(fx1, 0.0f));
        h2[2 * j + 1] = pack2(fmaxf(fy0, 0.0f), fmaxf(fy1, 0.0f));
    }

    // Layer 2: 4 output columns per group -> 4 independent FMA2 chains + float4 store.
    float4* outp = (float4*)(out + (long long)i * HD);
#pragma unroll 1
    for (int n = 0; n < HD; n += 4) {
        const ulonglong2* w0 = (const ulonglong2*)(sW2 + (n + 0) * HD);
        const ulonglong2* w1 = (const ulonglong2*)(sW2 + (n + 1) * HD);
        const ulonglong2* w2 = (const ulonglong2*)(sW2 + (n + 2) * HD);
        const ulonglong2* w3 = (const ulonglong2*)(sW2 + (n + 3) * HD);
        u64 a0 = 0ull, a1 = 0ull, a2 = 0ull, a3 = 0ull;
#pragma unroll
        for (int k = 0; k < 16; k++) {
            u64 hx = h2[2 * k + 0];
            u64 hy = h2[2 * k + 1];
            ulonglong2 ww0 = w0[k];
            ulonglong2 ww1 = w1[k];
            ulonglong2 ww2 = w2[k];
            ulonglong2 ww3 = w3[k];
            a0 = fma2(hx, ww0.x, a0); a0 = fma2(hy, ww0.y, a0);
            a1 = fma2(hx, ww1.x, a1); a1 = fma2(hy, ww1.y, a1);
            a2 = fma2(hx, ww2.x, a2); a2 = fma2(hy, ww2.y, a2);
            a3 = fma2(hx, ww3.x, a3); a3 = fma2(hy, ww3.y, a3);
        }
        float x0, x1, y0, y1, z0, z1, w0f, w1f;
        unpack2(a0, x0, x1);
        unpack2(a1, y0, y1);
        unpack2(a2, z0, z1);
        unpack2(a3, w0f, w1f);
        float4 r;
        r.x = x0 + x1 + sb2[n + 0];
        r.y = y0 + y1 + sb2[n + 1];
        r.z = z0 + z1 + sb2[n + 2];
        r.w = w0f + w1f + sb2[n + 3];
        outp[n >> 2] = r;
    }
}

// ---------------------------------------------------------------------------
// Launch. Inputs (metadata order): seqs, query_tok, embed, W1, b1, W2, b2.
// ---------------------------------------------------------------------------
extern "C" void kernel_launch(void* const* d_in, const int* in_sizes, int n_in,
                              void* d_out, int out_size) {
    const int*   seqs  = (const int*)d_in[0];
    const int*   qtok  = (const int*)d_in[1];
    const float* embed = (const float*)d_in[2];
    const float* W1    = (const float*)d_in[3];
    const float* b1    = (const float*)d_in[4];
    const float* W2    = (const float*)d_in[5];
    const float* b2    = (const float*)d_in[6];
    float* out = (float*)d_out;

    int Bn = in_sizes[1];                 // query_tok element count == batch
    precompute_tables<<<VOC, HD>>>(embed, W1, b1);

    int smem_bytes = (2 * VOC * PADS + HD * HD + HD) * (int)sizeof(float);  // 51456
    cudaFuncSetAttribute(lru_main, cudaFuncAttributeMaxDynamicSharedMemorySize, smem_bytes);

    int grid = (Bn + 255) / 256;
    lru_main<<<grid, 256, smem_bytes>>>(seqs, qtok, W2, b2, out, Bn);
}

// round 2
// speedup vs baseline: 1.1601x; 1.1601x over previous
#include <cuda_runtime.h>

#define HD    64
#define VOC   64
#define SEQ   48
#define MSL   4
#define PADS  68     // token-table row stride (spreads banks for random-token gathers)
#define PADH  68     // sH row stride: 68 floats = 272B = 17 x 16B granules -> conflict-free
#define TILE  256    // rows per tile
#define NTHR  256

typedef unsigned long long u64;

// Precomputed layer-1 tables (device-global scratch; no allocation).
__device__ float gTA[VOC * HD];   // embed[v] @ W1[:, :64]^T + b1
__device__ float gTB[VOC * HD];   // 0.25 * embed[v] @ W1[:, 64:]^T

__device__ __forceinline__ u64 fma2(u64 a, u64 b, u64 c) {
    u64 d;
    asm("fma.rn.f32x2 %0, %1, %2, %3;" : "=l"(d) : "l"(a), "l"(b), "l"(c));
    return d;
}
__device__ __forceinline__ u64 add2(u64 a, u64 b) {
    u64 d;
    asm("add.rn.f32x2 %0, %1, %2;" : "=l"(d) : "l"(a), "l"(b));
    return d;
}
__device__ __forceinline__ void unpack2(u64 v, float& x, float& y) {
    asm("mov.b64 {%0, %1}, %2;" : "=f"(x), "=f"(y) : "l"(v));
}
__device__ __forceinline__ u64 pack2(float x, float y) {
    u64 v;
    asm("mov.b64 %0, {%1, %2};" : "=l"(v) : "f"(x), "f"(y));
    return v;
}

// ---------------------------------------------------------------------------
// Kernel 1: build the 64x64 layer-1 tables. Negligible cost.
// ---------------------------------------------------------------------------
__global__ void precompute_tables(const float* __restrict__ embed,
                                  const float* __restrict__ W1,
                                  const float* __restrict__ b1) {
    int v = blockIdx.x;
    int j = threadIdx.x;
    __shared__ float e[HD];
    if (j < HD) e[j] = embed[v * HD + j];
    __syncthreads();

    float sa = b1[j];
    float sb = 0.0f;
    const float* w = W1 + j * (2 * HD);
#pragma unroll
    for (int d = 0; d < HD; d++) {
        sa = fmaf(e[d], w[d], sa);
        sb = fmaf(e[d], w[HD + d], sb);
    }
    gTA[v * HD + j] = sa;
    gTB[v * HD + j] = 0.25f * sb;
}

// ---------------------------------------------------------------------------
// Kernel 2: persistent. Per tile of 256 rows:
//   Phase 1: 1 thread/row gathers layer-1 from tables -> relu -> sH.
//   Phase 2: register-tiled GEMM out[256x64] = sH @ W2^T (+b2).
//            thread(w,l): rows l+32i (i<8), cols 8w..8w+7; acc = packed col-pairs.
// ---------------------------------------------------------------------------
__global__ void __launch_bounds__(NTHR, 1)
lru_main(const int* __restrict__ seqs,
         const int* __restrict__ query_tok,
         const float* __restrict__ W2,
         const float* __restrict__ b2,
         float* __restrict__ out,
         int Bn, int ntiles) {
    extern __shared__ float smem[];
    float* sTA  = smem;                       // VOC*PADS
    float* sTB  = sTA  + VOC * PADS;          // VOC*PADS
    float* sW2T = sTB  + VOC * PADS;          // [k][c] 64*64
    float* sb2  = sW2T + HD * HD;             // 64
    float* sH   = sb2  + HD;                  // TILE*PADH

    const int t = threadIdx.x;

    // One-time init: tables (padded), W2 transposed, bias.
    for (int idx = t; idx < VOC * HD; idx += NTHR) {
        int r = idx >> 6, c = idx & 63;
        sTA[r * PADS + c] = gTA[idx];
        sTB[r * PADS + c] = gTB[idx];
        sW2T[c * HD + r]  = W2[idx];          // W2[n][k] -> sW2T[k][n]
    }
    if (t < HD) sb2[t] = b2[t];
    __syncthreads();

    const int lane = t & 31;
    const int warp = t >> 5;

    // Per-thread bias for its 8 columns.
    float bb[8];
#pragma unroll
    for (int c = 0; c < 8; c++) bb[c] = sb2[warp * 8 + c];

    for (int tile = blockIdx.x; tile < ntiles; tile += gridDim.x) {
        // ---------------- Phase 1: build sH ----------------
        {
            int g = tile * TILE + t;          // global row
            if (g < Bn) {
                int q = query_tok[g];
                // tokens 43..46 of the row: two aligned int4 loads, one 32B sector
                const int4* sp = (const int4*)(seqs + (long long)g * SEQ + 40);
                int4 pa = sp[0];              // ints 40..43
                int4 pb = sp[1];              // ints 44..47
                int t0 = pa.w, t1 = pb.x, t2 = pb.y, t3 = pb.z;

                const ulonglong2* A  = (const ulonglong2*)(sTA + q  * PADS);
                const ulonglong2* B0 = (const ulonglong2*)(sTB + t0 * PADS);
                const ulonglong2* B1 = (const ulonglong2*)(sTB + t1 * PADS);
                const ulonglong2* B2 = (const ulonglong2*)(sTB + t2 * PADS);
                const ulonglong2* B3 = (const ulonglong2*)(sTB + t3 * PADS);

                ulonglong2* hrow = (ulonglong2*)(sH + t * PADH);
#pragma unroll
                for (int j = 0; j < 16; j++) {
                    ulonglong2 a  = A[j];
                    ulonglong2 p0 = B0[j], p1 = B1[j], p2 = B2[j], p3 = B3[j];
                    u64 sx = add2(add2(a.x, p0.x), add2(add2(p1.x, p2.x), p3.x));
                    u64 sy = add2(add2(a.y, p0.y), add2(add2(p1.y, p2.y), p3.y));
                    float fx0, fx1, fy0, fy1;
                    unpack2(sx, fx0, fx1);
                    unpack2(sy, fy0, fy1);
                    ulonglong2 hv;
                    hv.x = pack2(fmaxf(fx0, 0.0f), fmaxf(fx1, 0.0f));
                    hv.y = pack2(fmaxf(fy0, 0.0f), fmaxf(fy1, 0.0f));
                    hrow[j] = hv;
                }
            }
        }
        __syncthreads();

        // ---------------- Phase 2: register-tiled GEMM ----------------
        {
            u64 acc[8][4];
#pragma unroll
            for (int i = 0; i < 8; i++)
#pragma unroll
                for (int c = 0; c < 4; c++) acc[i][c] = 0ull;

            const float* w2base = sW2T + warp * 8;

#pragma unroll 1
            for (int kb = 0; kb < HD; kb += 4) {
                float4 hq[8];
#pragma unroll
                for (int i = 0; i < 8; i++)
                    hq[i] = *(const float4*)(sH + (lane + 32 * i) * PADH + kb);

#pragma unroll
                for (int kk = 0; kk < 4; kk++) {
                    const ulonglong2* wp = (const ulonglong2*)(w2base + (kb + kk) * HD);
                    ulonglong2 wa = wp[0];    // cols (8w,8w+1),(8w+2,8w+3)
                    ulonglong2 wb = wp[1];    // cols (8w+4,8w+5),(8w+6,8w+7)
#pragma unroll
                    for (int i = 0; i < 8; i++) {
                        float hv = (kk == 0) ? hq[i].x :
                                   (kk == 1) ? hq[i].y :
                                   (kk == 2) ? hq[i].z : hq[i].w;
                        u64 hh = pack2(hv, hv);
                        acc[i][0] = fma2(hh, wa.x, acc[i][0]);
                        acc[i][1] = fma2(hh, wa.y, acc[i][1]);
                        acc[i][2] = fma2(hh, wb.x, acc[i][2]);
                        acc[i][3] = fma2(hh, wb.y, acc[i][3]);
                    }
                }
            }

            // Epilogue: acc pairs are complete dot products per column.
#pragma unroll
            for (int i = 0; i < 8; i++) {
                int g = tile * TILE + lane + 32 * i;
                if (g < Bn) {
                    float x0, x1, y0, y1, z0, z1, u0, u1;
                    unpack2(acc[i][0], x0, x1);
                    unpack2(acc[i][1], y0, y1);
                    unpack2(acc[i][2], z0, z1);
                    unpack2(acc[i][3], u0, u1);
                    float4 r0, r1;
                    r0.x = x0 + bb[0]; r0.y = x1 + bb[1];
                    r0.z = y0 + bb[2]; r0.w = y1 + bb[3];
                    r1.x = z0 + bb[4]; r1.y = z1 + bb[5];
                    r1.z = u0 + bb[6]; r1.w = u1 + bb[7];
                    float* op = out + (long long)g * HD + warp * 8;
                    *(float4*)op       = r0;
                    *(float4*)(op + 4) = r1;
                }
            }
        }
        __syncthreads();   // protect sH before next tile's phase 1
    }
}

// ---------------------------------------------------------------------------
// Launch. Inputs (metadata order): seqs, query_tok, embed, W1, b1, W2, b2.
// ---------------------------------------------------------------------------
extern "C" void kernel_launch(void* const* d_in, const int* in_sizes, int n_in,
                              void* d_out, int out_size) {
    const int*   seqs  = (const int*)d_in[0];
    const int*   qtok  = (const int*)d_in[1];
    const float* embed = (const float*)d_in[2];
    const float* W1    = (const float*)d_in[3];
    const float* b1    = (const float*)d_in[4];
    const float* W2    = (const float*)d_in[5];
    const float* b2    = (const float*)d_in[6];
    float* out = (float*)d_out;

    int Bn = in_sizes[1];
    int ntiles = (Bn + TILE - 1) / TILE;

    precompute_tables<<<VOC, HD>>>(embed, W1, b1);

    int smem_bytes = (2 * VOC * PADS + HD * HD + HD + TILE * PADH) * (int)sizeof(float);
    cudaFuncSetAttribute(lru_main, cudaFuncAttributeMaxDynamicSharedMemorySize, smem_bytes);

    int grid = 152;                      // persistent: 1 CTA per SM on GB300
    if (grid > ntiles) grid = ntiles;
    lru_main<<<grid, NTHR, smem_bytes>>>(seqs, qtok, W2, b2, out, Bn, ntiles);
}

// round 6
// speedup vs baseline: 1.5461x; 1.3327x over previous
#include <cuda_runtime.h>

#define HD    64
#define VOC   64
#define SEQ   48
#define PADS  68     // table row stride: 17 x 16B granules (odd) -> conflict-free
#define PADH  68     // sH / sOut row stride, same property
#define TILE  256
#define NTHR  512

typedef unsigned long long u64;

__device__ float gTA[VOC * HD];   // embed[v] @ W1[:, :64]^T + b1
__device__ float gTB[VOC * HD];   // 0.25 * embed[v] @ W1[:, 64:]^T

__device__ __forceinline__ u64 fma2(u64 a, u64 b, u64 c) {
    u64 d;
    asm("fma.rn.f32x2 %0, %1, %2, %3;" : "=l"(d) : "l"(a), "l"(b), "l"(c));
    return d;
}
__device__ __forceinline__ u64 add2(u64 a, u64 b) {
    u64 d;
    asm("add.rn.f32x2 %0, %1, %2;" : "=l"(d) : "l"(a), "l"(b));
    return d;
}
__device__ __forceinline__ void unpack2(u64 v, float& x, float& y) {
    asm("mov.b64 {%0, %1}, %2;" : "=f"(x), "=f"(y) : "l"(v));
}
__device__ __forceinline__ u64 pack2(float x, float y) {
    u64 v;
    asm("mov.b64 %0, {%1, %2};" : "=l"(v) : "f"(x), "f"(y));
    return v;
}

// ---------------------------------------------------------------------------
// Kernel 1: build the 64x64 layer-1 tables. Negligible cost.
// ---------------------------------------------------------------------------
__global__ void precompute_tables(const float* __restrict__ embed,
                                  const float* __restrict__ W1,
                                  const float* __restrict__ b1) {
    int v = blockIdx.x;
    int j = threadIdx.x;
    __shared__ float e[HD];
    if (j < HD) e[j] = embed[v * HD + j];
    __syncthreads();

    float sa = b1[j];
    float sb = 0.0f;
    const float* w = W1 + j * (2 * HD);
#pragma unroll
    for (int d = 0; d < HD; d++) {
        sa = fmaf(e[d], w[d], sa);
        sb = fmaf(e[d], w[HD + d], sb);
    }
    gTA[v * HD + j] = sa;
    gTB[v * HD + j] = 0.25f * sb;
}

// ---------------------------------------------------------------------------
// Kernel 2: persistent, 512 threads (16 warps). Per tile of 256 rows:
//   P1: 8 lanes/row cooperative gather (conflict-free LDS) -> relu -> sH
//       tokens for all 4 row-passes prefetched (MLP ~12).
//   P2: register-tiled GEMM: warp (w&7)->8 cols, (w>>3)->128-row half;
//       thread: 4 rows x 8 cols packed f32x2 accumulators. Results -> sOut.
//   Copy-out of previous tile's sOut overlaps next P1 (coalesced STG).
// ---------------------------------------------------------------------------
__global__ void __launch_bounds__(NTHR, 1)
lru_main(const int* __restrict__ seqs,
         const int* __restrict__ query_tok,
         const float* __restrict__ W2,
         const float* __restrict__ b2,
         float* __restrict__ out,
         int Bn, int ntiles) {
    extern __shared__ float smem[];
    float* sTA  = smem;                       // VOC*PADS
    float* sTB  = sTA  + VOC * PADS;          // VOC*PADS
    float* sW2T = sTB  + VOC * PADS;          // [k][n] 64*64
    float* sb2  = sW2T + HD * HD;             // 64
    float* sH   = sb2  + HD;                  // TILE*PADH
    float* sOut = sH   + TILE * PADH;         // TILE*PADH

    const int t    = threadIdx.x;
    const int lane = t & 31;
    const int warp = t >> 5;

    // One-time init.
    for (int idx = t; idx < VOC * HD; idx += NTHR) {
        int r = idx >> 6, c = idx & 63;
        sTA[r * PADS + c] = gTA[idx];
        sTB[r * PADS + c] = gTB[idx];
        sW2T[c * HD + r]  = W2[idx];          // W2[n][k] -> sW2T[k][n]
    }
    if (t < HD) sb2[t] = b2[t];
    __syncthreads();

    // P2 mapping: warp (w&7) -> cols 8*(w&7); (w>>3) -> row half.
    const int colg   = (warp & 7) * 8;
    const int rbase2 = (warp >> 3) * 128;
    float bb[8];
#pragma unroll
    for (int c = 0; c < 8; c++) bb[c] = sb2[colg + c];

    // P1 mapping: 8 lanes per row; 4 rows per warp per pass; 4 passes.
    const int rr   = lane >> 3;               // 0..3 row-within-warp
    const int jj   = lane & 7;                // 0..7 j-position
    const int prow = warp * 4 + rr;           // 0..63 row within 64-row pass

    int tq[4], tk0[4], tk1[4], tk2[4], tk3[4];
    bool have_prev = false;
    int  prev_tile = 0;

    for (int tile = blockIdx.x; tile < ntiles; tile += gridDim.x) {
        // ---- Prefetch tokens for all 4 passes (independent loads) ----
#pragma unroll
        for (int p = 0; p < 4; p++) {
            int g = tile * TILE + p * 64 + prow;
            if (g >= Bn) g = Bn - 1;
            tq[p] = query_tok[g];
            const int4* sp = (const int4*)(seqs + (long long)g * SEQ + 40);
            int4 pa = sp[0];                  // ints 40..43
            int4 pb = sp[1];                  // ints 44..47
            tk0[p] = pa.w; tk1[p] = pb.x; tk2[p] = pb.y; tk3[p] = pb.z;
        }

        // ---- Copy-out previous tile (coalesced; overlaps token latency) ----
        if (have_prev) {
#pragma unroll
            for (int e = 0; e < (TILE * HD / 4) / NTHR; e++) {   // 8 iters
                int idx = t + e * NTHR;                          // float4 index
                int r = idx >> 4;
                int c = (idx & 15) << 2;
                int g = prev_tile * TILE + r;
                if (g < Bn)
                    *(float4*)(out + (long long)g * HD + c) =
                        *(const float4*)(sOut + r * PADH + c);
            }
        }

        // ---- P1: gather + relu into sH ----
#pragma unroll
        for (int p = 0; p < 4; p++) {
            int row = p * 64 + prow;
            const ulonglong2* A  = (const ulonglong2*)(sTA + tq[p]  * PADS);
            const ulonglong2* B0 = (const ulonglong2*)(sTB + tk0[p] * PADS);
            const ulonglong2* B1 = (const ulonglong2*)(sTB + tk1[p] * PADS);
            const ulonglong2* B2 = (const ulonglong2*)(sTB + tk2[p] * PADS);
            const ulonglong2* B3 = (const ulonglong2*)(sTB + tk3[p] * PADS);
#pragma unroll
            for (int s = 0; s < 2; s++) {
                int j = jj + s * 8;
                ulonglong2 a  = A[j];
                ulonglong2 p0 = B0[j], p1 = B1[j], p2 = B2[j], p3 = B3[j];
                u64 sx = add2(add2(a.x, p0.x), add2(add2(p1.x, p2.x), p3.x));
                u64 sy = add2(add2(a.y, p0.y), add2(add2(p1.y, p2.y), p3.y));
                float fx0, fx1, fy0, fy1;
                unpack2(sx, fx0, fx1);
                unpack2(sy, fy0, fy1);
                ulonglong2 hv;
                hv.x = pack2(fmaxf(fx0, 0.0f), fmaxf(fx1, 0.0f));
                hv.y = pack2(fmaxf(fy0, 0.0f), fmaxf(fy1, 0.0f));
                *(ulonglong2*)(sH + row * PADH + j * 4) = hv;
            }
        }
        __syncthreads();

        // ---- P2: register-tiled GEMM -> sOut ----
        {
            u64 acc[4][4];
#pragma unroll
            for (int i = 0; i < 4; i++)
#pragma unroll
                for (int c = 0; c < 4; c++) acc[i][c] = 0ull;

#pragma unroll 1
            for (int kb = 0; kb < HD; kb += 4) {
                float4 hq[4];
#pragma unroll
                for (int i = 0; i < 4; i++)
                    hq[i] = *(const float4*)(sH + (rbase2 + lane + 32 * i) * PADH + kb);

#pragma unroll
                for (int kk = 0; kk < 4; kk++) {
                    const ulonglong2* wp =
                        (const ulonglong2*)(sW2T + (kb + kk) * HD + colg);
                    ulonglong2 wa = wp[0];    // cols colg..colg+3
                    ulonglong2 wb = wp[1];    // cols colg+4..colg+7
#pragma unroll
                    for (int i = 0; i < 4; i++) {
                        float hv = (kk == 0) ? hq[i].x :
                                   (kk == 1) ? hq[i].y :
                                   (kk == 2) ? hq[i].z : hq[i].w;
                        u64 hh = pack2(hv, hv);
                        acc[i][0] = fma2(hh, wa.x, acc[i][0]);
                        acc[i][1] = fma2(hh, wa.y, acc[i][1]);
                        acc[i][2] = fma2(hh, wb.x, acc[i][2]);
                        acc[i][3] = fma2(hh, wb.y, acc[i][3]);
                    }
                }
            }

            // Epilogue: bias + store to sOut (conflict-free: odd granule stride).
#pragma unroll
            for (int i = 0; i < 4; i++) {
                int r = rbase2 + lane + 32 * i;
                float x0, x1, y0, y1, z0, z1, u0, u1;
                unpack2(acc[i][0], x0, x1);
                unpack2(acc[i][1], y0, y1);
                unpack2(acc[i][2], z0, z1);
                unpack2(acc[i][3], u0, u1);
                float4 r0, r1;
                r0.x = x0 + bb[0]; r0.y = x1 + bb[1];
                r0.z = y0 + bb[2]; r0.w = y1 + bb[3];
                r1.x = z0 + bb[4]; r1.y = z1 + bb[5];
                r1.z = u0 + bb[6]; r1.w = u1 + bb[7];
                float* op = sOut + r * PADH + colg;
                *(float4*)op       = r0;
                *(float4*)(op + 4) = r1;
            }
        }
        __syncthreads();

        have_prev = true;
        prev_tile = tile;
    }

    // ---- Final copy-out for the last tile this CTA processed ----
    if (have_prev) {
#pragma unroll
        for (int e = 0; e < (TILE * HD / 4) / NTHR; e++) {
            int idx = t + e * NTHR;
            int r = idx >> 4;
            int c = (idx & 15) << 2;
            int g = prev_tile * TILE + r;
            if (g < Bn)
                *(float4*)(out + (long long)g * HD + c) =
                    *(const float4*)(sOut + r * PADH + c);
        }
    }
}

// ---------------------------------------------------------------------------
// Launch. Inputs (metadata order): seqs, query_tok, embed, W1, b1, W2, b2.
// ---------------------------------------------------------------------------
extern "C" void kernel_launch(void* const* d_in, const int* in_sizes, int n_in,
                              void* d_out, int out_size) {
    const int*   seqs  = (const int*)d_in[0];
    const int*   qtok  = (const int*)d_in[1];
    const float* embed = (const float*)d_in[2];
    const float* W1    = (const float*)d_in[3];
    const float* b1    = (const float*)d_in[4];
    const float* W2    = (const float*)d_in[5];
    const float* b2    = (const float*)d_in[6];
    float* out = (float*)d_out;

    int Bn = in_sizes[1];
    int ntiles = (Bn + TILE - 1) / TILE;

    precompute_tables<<<VOC, HD>>>(embed, W1, b1);

    int smem_bytes = (2 * VOC * PADS + HD * HD + HD + 2 * TILE * PADH) * (int)sizeof(float);
    cudaFuncSetAttribute(lru_main, cudaFuncAttributeMaxDynamicSharedMemorySize, smem_bytes);

    int grid = 152;
    if (grid > ntiles) grid = ntiles;
    lru_main<<<grid, NTHR, smem_bytes>>>(seqs, qtok, W2, b2, out, Bn, ntiles);
}

// round 13
// speedup vs baseline: 2.1599x; 1.3970x over previous
#include <cuda_runtime.h>
#include <cuda_bf16.h>
#include <cstdint>

#define HD    64
#define VOC   64
#define SEQ   48
#define PADS  68      // f32 table row stride: 272B = 17 granules (odd) -> spreads banks
#define TILE  256
#define NTHR  512
#define HSTR  144     // h row stride bytes (9 granules, odd) -> LDSM conflict-free
#define WSTR  144     // W2 row stride bytes

// ---- dynamic SMEM byte offsets ----
#define OFF_B2   0
#define OFF_TA   256
#define OFF_TB   (OFF_TA + VOC*PADS*4)       // 17664
#define OFF_WHI  (OFF_TB + VOC*PADS*4)       // 35072
#define OFF_WLO  (OFF_WHI + 64*WSTR)         // 44288
#define OFF_HHI  (OFF_WLO + 64*WSTR)         // 53504
#define OFF_HLO  (OFF_HHI + 256*HSTR)        // 90368
#define SMEM_BYTES (OFF_HLO + 256*HSTR)      // 127232

typedef unsigned long long u64;

__device__ float gTA[VOC * HD];   // embed[v] @ W1[:, :64]^T + b1
__device__ float gTB[VOC * HD];   // 0.25 * embed[v] @ W1[:, 64:]^T

// ---------------- PTX helpers (all non-arch-specific) ----------------
__device__ __forceinline__ u64 add2(u64 a, u64 b) {
    u64 d; asm("add.rn.f32x2 %0, %1, %2;" : "=l"(d) : "l"(a), "l"(b)); return d;
}
__device__ __forceinline__ void unpack2(u64 v, float& x, float& y) {
    asm("mov.b64 {%0, %1}, %2;" : "=f"(x), "=f"(y) : "l"(v));
}
__device__ __forceinline__ uint32_t smem_u32(const void* p) {
    uint32_t a;
    asm("{ .reg .u64 t; cvta.to.shared.u64 t, %1; cvt.u32.u64 %0, t; }" : "=r"(a) : "l"(p));
    return a;
}
__device__ __forceinline__ uint32_t cvt_bf16x2(float hi, float lo) {
    uint32_t r;
    asm("cvt.rn.bf16x2.f32 %0, %1, %2;" : "=r"(r) : "f"(hi), "f"(lo));
    return r;
}
__device__ __forceinline__ void sts64(uint32_t addr, uint32_t lo, uint32_t hi) {
    asm volatile("st.shared.v2.b32 [%0], {%1,%2};" :: "r"(addr), "r"(lo), "r"(hi) : "memory");
}
__device__ __forceinline__ void ldsm4(uint32_t* r, uint32_t addr) {
    asm volatile("ldmatrix.sync.aligned.m8n8.x4.shared.b16 {%0,%1,%2,%3}, [%4];"
                 : "=r"(r[0]), "=r"(r[1]), "=r"(r[2]), "=r"(r[3]) : "r"(addr));
}
__device__ __forceinline__ void mma16816(float* c, const uint32_t* a,
                                         uint32_t b0, uint32_t b1) {
    asm volatile("mma.sync.aligned.m16n8k16.row.col.f32.bf16.bf16.f32 "
                 "{%0,%1,%2,%3}, {%4,%5,%6,%7}, {%8,%9}, {%0,%1,%2,%3};"
                 : "+f"(c[0]), "+f"(c[1]), "+f"(c[2]), "+f"(c[3])
                 : "r"(a[0]), "r"(a[1]), "r"(a[2]), "r"(a[3]), "r"(b0), "r"(b1));
}

// ---------------------------------------------------------------------------
// Kernel 1: build the 64x64 layer-1 tables. Negligible cost.
// ---------------------------------------------------------------------------
__global__ void precompute_tables(const float* __restrict__ embed,
                                  const float* __restrict__ W1,
                                  const float* __restrict__ b1) {
    int v = blockIdx.x;
    int j = threadIdx.x;
    __shared__ float e[HD];
    if (j < HD) e[j] = embed[v * HD + j];
    __syncthreads();

    float sa = b1[j];
    float sb = 0.0f;
    const float* w = W1 + j * (2 * HD);
#pragma unroll
    for (int d = 0; d < HD; d++) {
        sa = fmaf(e[d], w[d], sa);
        sb = fmaf(e[d], w[HD + d], sb);
    }
    gTA[v * HD + j] = sa;
    gTB[v * HD + j] = 0.25f * sb;
}

// ---------------------------------------------------------------------------
// Kernel 2: persistent, 512 threads (16 warps). Per 256-row tile:
//   P1: table gather (f32) -> relu -> bf16 hi/lo split -> smem h tiles.
//   P2: warp-level HMMA: out[32x32 per warp] = hHi@Whi + hHi@Wlo + hLo@Whi,
//       f32 acc initialized with bias, direct st.v2 to gmem.
// ---------------------------------------------------------------------------
__global__ void __launch_bounds__(NTHR, 1)
lru_main(const int* __restrict__ seqs,
         const int* __restrict__ query_tok,
         const float* __restrict__ W2,
         const float* __restrict__ b2,
         float* __restrict__ out,
         int Bn, int ntiles) {
    extern __shared__ char smem[];
    const uint32_t sb = smem_u32(smem);
    float* sb2 = (float*)(smem + OFF_B2);
    float* sTA = (float*)(smem + OFF_TA);
    float* sTB = (float*)(smem + OFF_TB);

    const int t    = threadIdx.x;
    const int lane = t & 31;
    const int warp = t >> 5;

    // One-time init: f32 tables (padded) + W2 bf16 hi/lo + bias.
    for (int idx = t; idx < VOC * HD; idx += NTHR) {
        int r = idx >> 6, c = idx & 63;
        sTA[r * PADS + c] = gTA[idx];
        sTB[r * PADS + c] = gTB[idx];
        float w = W2[idx];                     // W2[n][k]: n=r, k=c
        __nv_bfloat16 bh = __float2bfloat16(w);
        float fh = __bfloat162float(bh);
        __nv_bfloat16 bl = __float2bfloat16(w - fh);
        *(__nv_bfloat16*)(smem + OFF_WHI + r * WSTR + 2 * c) = bh;
        *(__nv_bfloat16*)(smem + OFF_WLO + r * WSTR + 2 * c) = bl;
    }
    if (t < HD) sb2[t] = b2[t];
    __syncthreads();

    // ---- P2 mapping: warp -> rows [(w>>1)*32, +32), cols [(w&1)*32, +32) ----
    const int rbase = (warp >> 1) * 32;
    const int cb    = (warp & 1) * 32;
    float2 bias[4];
#pragma unroll
    for (int nt = 0; nt < 4; nt++) {
        int col = cb + nt * 8 + 2 * (lane & 3);
        bias[nt].x = sb2[col];
        bias[nt].y = sb2[col + 1];
    }
    // LDSM lane-address components (A: 16 rows x 2 k-halves; B: 2 n-tiles x 2 k-halves)
    const uint32_t aAddrBase = (uint32_t)((rbase + (lane & 15)) * HSTR + ((lane >> 4) & 1) * 16);
    const uint32_t bAddrBase = (uint32_t)((cb + ((lane >> 4) & 1) * 8 + (lane & 7)) * WSTR
                                          + ((lane >> 3) & 1) * 16);

    // ---- P1 mapping: 8 lanes/row, 4 rows/warp/pass, 4 passes ----
    const int rr   = lane >> 3;
    const int jj   = lane & 7;
    const int prow = warp * 4 + rr;

    // Token prefetch: 5 tokens (6 bits each) packed per pass into one int.
#define LOADTOKS(dst, tl)                                                   \
    do {                                                                    \
        _Pragma("unroll")                                                   \
        for (int p = 0; p < 4; p++) {                                       \
            int g = (tl) * TILE + p * 64 + prow;                            \
            if (g >= Bn) g = Bn - 1;                                        \
            int q = query_tok[g];                                           \
            const int4* sp = (const int4*)(seqs + (long long)g * SEQ + 40); \
            int4 pa = sp[0];                                                \
            int4 pb = sp[1];                                                \
            (dst)[p] = q | (pa.w << 6) | (pb.x << 12)                       \
                         | (pb.y << 18) | (pb.z << 24);                     \
        }                                                                   \
    } while (0)

    int pk[4];
    int tile = blockIdx.x;
    if (tile < ntiles) LOADTOKS(pk, tile);

    for (; tile < ntiles; tile += gridDim.x) {
        // ---------------- P1: gather + relu + hi/lo split -> smem ----------------
#pragma unroll
        for (int p = 0; p < 4; p++) {
            int pkp = pk[p];
            int row = p * 64 + prow;
            const ulonglong2* A  = (const ulonglong2*)(sTA + (pkp & 63) * PADS);
            const ulonglong2* B0 = (const ulonglong2*)(sTB + ((pkp >> 6) & 63) * PADS);
            const ulonglong2* B1 = (const ulonglong2*)(sTB + ((pkp >> 12) & 63) * PADS);
            const ulonglong2* B2 = (const ulonglong2*)(sTB + ((pkp >> 18) & 63) * PADS);
            const ulonglong2* B3 = (const ulonglong2*)(sTB + ((pkp >> 24) & 63) * PADS);
            uint32_t hdst = sb + (uint32_t)(row * HSTR);
#pragma unroll
            for (int s = 0; s < 2; s++) {
                int j = jj + 8 * s;                  // cols 4j..4j+3
                ulonglong2 a  = A[j];
                ulonglong2 p0 = B0[j], p1 = B1[j], p2 = B2[j], p3 = B3[j];
                u64 sx = add2(add2(a.x, p0.x), add2(add2(p1.x, p2.x), p3.x));
                u64 sy = add2(add2(a.y, p0.y), add2(add2(p1.y, p2.y), p3.y));
                float f0, f1, f2, f3;
                unpack2(sx, f0, f1);
                unpack2(sy, f2, f3);
                f0 = fmaxf(f0, 0.0f); f1 = fmaxf(f1, 0.0f);
                f2 = fmaxf(f2, 0.0f); f3 = fmaxf(f3, 0.0f);
                uint32_t hi01 = cvt_bf16x2(f1, f0);  // mem order: f0, f1
                uint32_t hi23 = cvt_bf16x2(f3, f2);
                float g0 = __uint_as_float(hi01 << 16);
                float g1 = __uint_as_float(hi01 & 0xFFFF0000u);
                float g2 = __uint_as_float(hi23 << 16);
                float g3 = __uint_as_float(hi23 & 0xFFFF0000u);
                uint32_t lo01 = cvt_bf16x2(f1 - g1, f0 - g0);
                uint32_t lo23 = cvt_bf16x2(f3 - g3, f2 - g2);
                sts64(hdst + OFF_HHI + 8 * j, hi01, hi23);
                sts64(hdst + OFF_HLO + 8 * j, lo01, lo23);
            }
        }

        // Prefetch next tile's tokens (overlaps P2 with DRAM latency).
        {
            int tn = tile + gridDim.x;
            if (tn < ntiles) LOADTOKS(pk, tn);
        }
        __syncthreads();

        // ---------------- P2: HMMA ----------------
        {
            float acc[2][4][4];
#pragma unroll
            for (int s = 0; s < 2; s++)
#pragma unroll
                for (int nt = 0; nt < 4; nt++) {
                    acc[s][nt][0] = bias[nt].x;
                    acc[s][nt][1] = bias[nt].y;
                    acc[s][nt][2] = bias[nt].x;
                    acc[s][nt][3] = bias[nt].y;
                }

            uint32_t Bf[4][2][4];                 // [ks][npair][4 regs]
            uint32_t Af[4][4];                    // [ks][4 regs]

#define LOADB(WOFF)                                                          \
            _Pragma("unroll")                                                \
            for (int ks = 0; ks < 4; ks++)                                   \
                _Pragma("unroll")                                            \
                for (int np = 0; np < 2; np++)                               \
                    ldsm4(Bf[ks][np],                                        \
                          sb + (WOFF) + bAddrBase + (uint32_t)(np * 16 * WSTR + ks * 32));

#define LOADA(HOFF, slab)                                                    \
            _Pragma("unroll")                                                \
            for (int ks = 0; ks < 4; ks++)                                   \
                ldsm4(Af[ks],                                                \
                      sb + (HOFF) + aAddrBase + (uint32_t)((slab) * 16 * HSTR + ks * 32));

#define MMABLK(slab)                                                         \
            _Pragma("unroll")                                                \
            for (int ks = 0; ks < 4; ks++)                                   \
                _Pragma("unroll")                                            \
                for (int nt = 0; nt < 4; nt++)                               \
                    mma16816(acc[slab][nt], Af[ks],                          \
                             Bf[ks][nt >> 1][(nt & 1) * 2],                  \
                             Bf[ks][nt >> 1][(nt & 1) * 2 + 1]);

            // hi @ Whi  and  lo @ Whi
            LOADB(OFF_WHI);
#pragma unroll
            for (int slab = 0; slab < 2; slab++) {
                LOADA(OFF_HHI, slab); MMABLK(slab);
                LOADA(OFF_HLO, slab); MMABLK(slab);
            }
            // hi @ Wlo
            LOADB(OFF_WLO);
#pragma unroll
            for (int slab = 0; slab < 2; slab++) {
                LOADA(OFF_HHI, slab); MMABLK(slab);
            }

            // Epilogue: direct coalesced-pair stores to gmem.
            long long base = (long long)tile * TILE + rbase;
#pragma unroll
            for (int s = 0; s < 2; s++)
#pragma unroll
                for (int nt = 0; nt < 4; nt++) {
                    long long r0 = base + s * 16 + (lane >> 2);
                    int col = cb + nt * 8 + 2 * (lane & 3);
                    if (r0 < Bn) {
                        float2 v; v.x = acc[s][nt][0]; v.y = acc[s][nt][1];
                        *(float2*)(out + r0 * HD + col) = v;
                    }
                    if (r0 + 8 < Bn) {
                        float2 v; v.x = acc[s][nt][2]; v.y = acc[s][nt][3];
                        *(float2*)(out + (r0 + 8) * HD + col) = v;
                    }
                }
        }
        __syncthreads();   // h tiles free for next P1
    }
}

// ---------------------------------------------------------------------------
// Launch. Inputs (metadata order): seqs, query_tok, embed, W1, b1, W2, b2.
// ---------------------------------------------------------------------------
extern "C" void kernel_launch(void* const* d_in, const int* in_sizes, int n_in,
                              void* d_out, int out_size) {
    const int*   seqs  = (const int*)d_in[0];
    const int*   qtok  = (const int*)d_in[1];
    const float* embed = (const float*)d_in[2];
    const float* W1    = (const float*)d_in[3];
    const float* b1    = (const float*)d_in[4];
    const float* W2    = (const float*)d_in[5];
    const float* b2    = (const float*)d_in[6];
    float* out = (float*)d_out;

    int Bn = in_sizes[1];
    int ntiles = (Bn + TILE - 1) / TILE;

    precompute_tables<<<VOC, HD>>>(embed, W1, b1);

    cudaFuncSetAttribute(lru_main, cudaFuncAttributeMaxDynamicSharedMemorySize, SMEM_BYTES);

    int grid = 152;
    if (grid > ntiles) grid = ntiles;
    lru_main<<<grid, NTHR, SMEM_BYTES>>>(seqs, qtok, W2, b2, out, Bn, ntiles);
}